// round 6
// baseline (speedup 1.0000x reference)
#include <cuda_runtime.h>
#include <cuda_bf16.h>

// Problem constants
// p1, p2: [B=2, C=32, D=96, H=96, W=96] fp32
// pool to S=8 per axis (block 12x12x12), L = 512 tokens of C=32 channels
// out: scalar = mean_b mean_{l,m} (cos_a[l,m] - cos_b[l,m])^2

#define BATCH 2
#define CH    32
#define DIM   96
#define SPOOL 8
#define LTOK  512          // 8*8*8
#define BLK   12           // 96/8
#define EPS   1e-8f

// Scratch: pooled tokens stored token-major: [tensor(2)][b(2)][l(512)][c(32)]
__device__ float g_pooled[2 * BATCH * LTOK * CH];
__device__ float g_acc;

// ---------------------------------------------------------------------------
// Kernel 1: pooling. One block per (tensor, b, c, pd, ph): reduces
// 12(d) x 12(h) x 96(w) floats into 8 pooled-w cells.
// blockDim = 96: thread t -> f4 = t%24 (float4 index along w), rs = t/24.
// Each float4 (w in [4j, 4j+4)) lies entirely in one pooled cell (12 = 3*4).
// ---------------------------------------------------------------------------
__global__ __launch_bounds__(96) void pool_kernel(const float* __restrict__ p1,
                                                  const float* __restrict__ p2)
{
    const int bid = blockIdx.x;
    if (bid == 0 && threadIdx.x == 0) g_acc = 0.0f;

    const int ph = bid & 7;
    const int pd = (bid >> 3) & 7;
    const int c  = (bid >> 6) & 31;
    const int b  = (bid >> 11) & 1;
    const int t  = bid >> 12;

    const float* __restrict__ in = (t == 0) ? p1 : p2;
    const float* __restrict__ base =
        in + ((size_t)(b * CH + c)) * (DIM * DIM * DIM)
           + (size_t)pd * BLK * DIM * DIM
           + (size_t)ph * BLK * DIM;

    const int tid = threadIdx.x;
    const int f4  = tid % 24;   // float4 index along w: w = 4*f4
    const int rs  = tid / 24;   // row sub-phase 0..3

    float acc = 0.0f;
    #pragma unroll 4
    for (int r = 0; r < 36; ++r) {
        const int row = r * 4 + rs;        // 0..143 over 12(d) x 12(h)
        const int d   = row / 12;
        const int h   = row - d * 12;
        const float4 v = *reinterpret_cast<const float4*>(
            base + (size_t)d * (DIM * DIM) + h * DIM + f4 * 4);
        acc += (v.x + v.y) + (v.z + v.w);
    }

    __shared__ float sh[96];
    sh[tid] = acc;
    __syncthreads();

    if (tid < SPOOL) {
        float s = 0.0f;
        #pragma unroll
        for (int r2 = 0; r2 < 4; ++r2)
            #pragma unroll
            for (int j = 0; j < 3; ++j)
                s += sh[r2 * 24 + tid * 3 + j];
        const int l = pd * 64 + ph * 8 + tid;   // flattened (pd,ph,pw)
        g_pooled[(((size_t)t * BATCH + b) * LTOK + l) * CH + c] =
            s * (1.0f / (BLK * BLK * BLK));
    }
}

// ---------------------------------------------------------------------------
// Kernel 2: cosine-sim matrices for both tensors + MSE accumulation.
// grid = 2 batches x 32 l-tiles (16 rows each). 256 threads = 16 rows x 16
// m-lanes; each thread handles one row and m = k*16 + mt for k in [0,32).
// Both token matrices for the batch live in shared with row stride 36 floats
// (36 mod 32 == 4 -> conflict-free LDS.128 pattern across 8 lanes).
// ---------------------------------------------------------------------------
#define STR 36
#define SIM_SMEM ((2 * LTOK * STR + 2 * LTOK) * (int)sizeof(float))

__global__ __launch_bounds__(256) void sim_kernel()
{
    extern __shared__ float sm[];
    float* shA = sm;                     // [512][36]
    float* shB = sm + LTOK * STR;        // [512][36]
    float* nA  = shB + LTOK * STR;       // [512]
    float* nB  = nA + LTOK;              // [512]

    const int b     = blockIdx.x >> 5;   // 0..1
    const int ltile = blockIdx.x & 31;   // 0..31

    const float* __restrict__ pa = g_pooled + ((size_t)(0 * BATCH + b) * LTOK) * CH;
    const float* __restrict__ pb = g_pooled + ((size_t)(1 * BATCH + b) * LTOK) * CH;

    for (int idx = threadIdx.x; idx < LTOK * CH; idx += 256) {
        const int l = idx >> 5;
        const int c = idx & 31;
        shA[l * STR + c] = pa[idx];
        shB[l * STR + c] = pb[idx];
    }
    __syncthreads();

    for (int l = threadIdx.x; l < LTOK; l += 256) {
        float sa = 0.0f, sb = 0.0f;
        #pragma unroll
        for (int c = 0; c < CH; ++c) {
            const float va = shA[l * STR + c];
            const float vb = shB[l * STR + c];
            sa += va * va;
            sb += vb * vb;
        }
        nA[l] = sqrtf(sa);
        nB[l] = sqrtf(sb);
    }
    __syncthreads();

    const int row = threadIdx.x >> 4;           // 0..15
    const int mt  = threadIdx.x & 15;           // 0..15
    const int l   = ltile * 16 + row;

    float4 fa[8], fb[8];
    #pragma unroll
    for (int i = 0; i < 8; ++i) {
        fa[i] = *reinterpret_cast<const float4*>(&shA[l * STR + i * 4]);
        fb[i] = *reinterpret_cast<const float4*>(&shB[l * STR + i * 4]);
    }
    const float nla = nA[l];
    const float nlb = nB[l];

    float local = 0.0f;
    #pragma unroll 4
    for (int k = 0; k < 32; ++k) {
        const int m = k * 16 + mt;
        float da = 0.0f, db = 0.0f;
        #pragma unroll
        for (int i = 0; i < 8; ++i) {
            const float4 ma = *reinterpret_cast<const float4*>(&shA[m * STR + i * 4]);
            da += fa[i].x * ma.x + fa[i].y * ma.y + fa[i].z * ma.z + fa[i].w * ma.w;
            const float4 mb = *reinterpret_cast<const float4*>(&shB[m * STR + i * 4]);
            db += fb[i].x * mb.x + fb[i].y * mb.y + fb[i].z * mb.z + fb[i].w * mb.w;
        }
        const float sa = da / fmaxf(nla * nA[m], EPS);
        const float sb = db / fmaxf(nlb * nB[m], EPS);
        const float diff = sa - sb;
        local += diff * diff;
    }

    // block reduce -> atomic add
    #pragma unroll
    for (int off = 16; off > 0; off >>= 1)
        local += __shfl_xor_sync(0xFFFFFFFFu, local, off);

    __shared__ float wsum[8];
    if ((threadIdx.x & 31) == 0) wsum[threadIdx.x >> 5] = local;
    __syncthreads();
    if (threadIdx.x == 0) {
        float s = 0.0f;
        #pragma unroll
        for (int i = 0; i < 8; ++i) s += wsum[i];
        atomicAdd(&g_acc, s);
    }
}

// ---------------------------------------------------------------------------
// Kernel 3: finalize scalar.
// ---------------------------------------------------------------------------
__global__ void finalize_kernel(float* __restrict__ out)
{
    out[0] = g_acc * (1.0f / ((float)LTOK * (float)LTOK * (float)BATCH));
}

// ---------------------------------------------------------------------------
extern "C" void kernel_launch(void* const* d_in, const int* in_sizes, int n_in,
                              void* d_out, int out_size)
{
    const float* p1 = (const float*)d_in[0];
    const float* p2 = (const float*)d_in[1];
    float* out = (float*)d_out;

    cudaFuncSetAttribute(sim_kernel, cudaFuncAttributeMaxDynamicSharedMemorySize,
                         SIM_SMEM);

    // 2 tensors x 2 batch x 32 ch x 8 pd x 8 ph = 8192 blocks
    pool_kernel<<<8192, 96>>>(p1, p2);
    sim_kernel<<<64, 256, SIM_SMEM>>>();
    finalize_kernel<<<1, 1>>>(out);
}

// round 7
// speedup vs baseline: 1.0714x; 1.0714x over previous
#include <cuda_runtime.h>
#include <cuda_bf16.h>

// p1, p2: [B=2, C=32, D=96, H=96, W=96] fp32
// pool to S=8 per axis (cells 12x12x12), L = 512 tokens of C=32 channels
// out scalar = mean_b mean_{l,m} (cos_a[l,m] - cos_b[l,m])^2

#define BATCH 2
#define CH    32
#define DIM   96
#define SPOOL 8
#define LTOK  512
#define BLK   12
#define EPS   1e-8f

// pooled tokens token-major: [tensor(2)][b(2)][l(512)][c(32)]
__device__ float g_pooled[2 * BATCH * LTOK * CH];
__device__ float g_acc;
__device__ unsigned int g_cnt;

// ---------------------------------------------------------------------------
// Kernel 1: pooling. One block per (tensor, b, c, pd, ph).
// 96 threads: f4 = tid%24 (float4 along w), rs = tid/24 picks a CONTIGUOUS
// chunk of rows: d in [3*rs, 3*rs+3), h in [0,12). All 36 loads are affine
// immediate offsets from one base pointer -> front-batched LDG.128, no divs.
// ---------------------------------------------------------------------------
__global__ __launch_bounds__(96) void pool_kernel(const float* __restrict__ p1,
                                                  const float* __restrict__ p2)
{
    const int bid = blockIdx.x;
    if (bid == 0 && threadIdx.x == 0) { g_acc = 0.0f; g_cnt = 0u; }

    const int ph = bid & 7;
    const int pd = (bid >> 3) & 7;
    const int c  = (bid >> 6) & 31;
    const int b  = (bid >> 11) & 1;
    const int t  = bid >> 12;

    const float* __restrict__ in = (t == 0) ? p1 : p2;

    const int tid = threadIdx.x;
    const int f4  = tid % 24;   // w = 4*f4
    const int rs  = tid / 24;   // 0..3 -> d chunk [3rs, 3rs+3)

    const float* __restrict__ base =
        in + ((size_t)(b * CH + c)) * (DIM * DIM * DIM)
           + (size_t)(pd * BLK + 3 * rs) * (DIM * DIM)
           + (size_t)ph * BLK * DIM
           + f4 * 4;

    float acc = 0.0f;
    #pragma unroll
    for (int d2 = 0; d2 < 3; ++d2) {
        #pragma unroll
        for (int h = 0; h < 12; ++h) {
            const float4 v = *reinterpret_cast<const float4*>(
                base + d2 * (DIM * DIM) + h * DIM);
            acc += (v.x + v.y) + (v.z + v.w);
        }
    }

    __shared__ float sh[96];
    sh[tid] = acc;
    __syncthreads();

    if (tid < SPOOL) {
        float s = 0.0f;
        #pragma unroll
        for (int r2 = 0; r2 < 4; ++r2)
            #pragma unroll
            for (int j = 0; j < 3; ++j)
                s += sh[r2 * 24 + tid * 3 + j];
        const int l = pd * 64 + ph * 8 + tid;
        g_pooled[(((size_t)t * BATCH + b) * LTOK + l) * CH + c] =
            s * (1.0f / (BLK * BLK * BLK));
    }
}

// ---------------------------------------------------------------------------
// Kernel 2: cosine-sim MSE, fused finalize.
// 128 blocks = 2 batches x 64 l-tiles (8 rows each). 256 threads =
// 8 rows x 32 m-lanes (one warp per row). Token rows normalized in shared
// once (u = f/||f||; eps never binds: ||f||^2 ~ 0.018 >> 1e-8), so the
// inner loop is pure dot + diff^2. Row stride 36 floats -> LDS.128
// conflict-free across the 8-lane phases.
// ---------------------------------------------------------------------------
#define STR 36
#define SIM_BLOCKS 128
#define SIM_SMEM (2 * LTOK * STR * (int)sizeof(float))

__global__ __launch_bounds__(256) void sim_kernel(float* __restrict__ out)
{
    extern __shared__ float sm[];
    float* shA = sm;               // [512][36]
    float* shB = sm + LTOK * STR;  // [512][36]

    const int b     = blockIdx.x >> 6;   // 0..1
    const int ltile = blockIdx.x & 63;   // 0..63

    const float* __restrict__ pa = g_pooled + ((size_t)(0 * BATCH + b) * LTOK) * CH;
    const float* __restrict__ pb = g_pooled + ((size_t)(1 * BATCH + b) * LTOK) * CH;

    for (int idx = threadIdx.x; idx < LTOK * CH; idx += 256) {
        const int l = idx >> 5;
        const int c = idx & 31;
        shA[l * STR + c] = pa[idx];
        shB[l * STR + c] = pb[idx];
    }
    __syncthreads();

    // normalize rows in place
    for (int l = threadIdx.x; l < LTOK; l += 256) {
        float sa = 0.0f, sb = 0.0f;
        #pragma unroll
        for (int c = 0; c < CH; ++c) {
            const float va = shA[l * STR + c];
            const float vb = shB[l * STR + c];
            sa += va * va;
            sb += vb * vb;
        }
        const float ra = 1.0f / sqrtf(fmaxf(sa, EPS));
        const float rb = 1.0f / sqrtf(fmaxf(sb, EPS));
        #pragma unroll
        for (int c = 0; c < CH; ++c) {
            shA[l * STR + c] *= ra;
            shB[l * STR + c] *= rb;
        }
    }
    __syncthreads();

    const int row = threadIdx.x >> 5;  // 0..7 (one warp per row)
    const int mt  = threadIdx.x & 31;  // 0..31
    const int l   = ltile * 8 + row;

    float4 ua[8], ub[8];
    #pragma unroll
    for (int i = 0; i < 8; ++i) {
        ua[i] = *reinterpret_cast<const float4*>(&shA[l * STR + i * 4]);
        ub[i] = *reinterpret_cast<const float4*>(&shB[l * STR + i * 4]);
    }

    float local = 0.0f;
    #pragma unroll 4
    for (int k = 0; k < 16; ++k) {
        const int m = k * 32 + mt;
        float da = 0.0f, db = 0.0f;
        #pragma unroll
        for (int i = 0; i < 8; ++i) {
            const float4 ma = *reinterpret_cast<const float4*>(&shA[m * STR + i * 4]);
            da += ua[i].x * ma.x + ua[i].y * ma.y + ua[i].z * ma.z + ua[i].w * ma.w;
            const float4 mb = *reinterpret_cast<const float4*>(&shB[m * STR + i * 4]);
            db += ub[i].x * mb.x + ub[i].y * mb.y + ub[i].z * mb.z + ub[i].w * mb.w;
        }
        const float diff = da - db;
        local += diff * diff;
    }

    // block reduce
    #pragma unroll
    for (int off = 16; off > 0; off >>= 1)
        local += __shfl_xor_sync(0xFFFFFFFFu, local, off);

    __shared__ float wsum[8];
    if ((threadIdx.x & 31) == 0) wsum[threadIdx.x >> 5] = local;
    __syncthreads();

    if (threadIdx.x == 0) {
        float s = 0.0f;
        #pragma unroll
        for (int i = 0; i < 8; ++i) s += wsum[i];
        atomicAdd(&g_acc, s);
        __threadfence();
        const unsigned int old = atomicAdd(&g_cnt, 1u);
        if (old == SIM_BLOCKS - 1) {
            const float total = *((volatile float*)&g_acc);
            out[0] = total * (1.0f / ((float)LTOK * (float)LTOK * (float)BATCH));
        }
    }
}

// ---------------------------------------------------------------------------
extern "C" void kernel_launch(void* const* d_in, const int* in_sizes, int n_in,
                              void* d_out, int out_size)
{
    const float* p1 = (const float*)d_in[0];
    const float* p2 = (const float*)d_in[1];
    float* out = (float*)d_out;

    cudaFuncSetAttribute(sim_kernel, cudaFuncAttributeMaxDynamicSharedMemorySize,
                         SIM_SMEM);

    pool_kernel<<<8192, 96>>>(p1, p2);             // 2*2*32*8*8 blocks
    sim_kernel<<<SIM_BLOCKS, 256, SIM_SMEM>>>(out);
}

// round 8
// speedup vs baseline: 1.2012x; 1.1211x over previous
#include <cuda_runtime.h>
#include <cuda_bf16.h>

// p1, p2: [B=2, C=32, D=96, H=96, W=96] fp32
// pool to S=8 (cells 12^3), L = 512 tokens, C = 32 channels.
// loss = mean_b mean_{l,m} (cos_a[l,m] - cos_b[l,m])^2
//      = (1/(L^2 B)) * sum_b [ ||Ga||F^2 + ||Gb||F^2 - 2||Gx||F^2 ]
// with Ga = Ua^T Ua, Gb = Ub^T Ub, Gx = Ua^T Ub over unit-normalized tokens.

#define BATCH 2
#define CH    32
#define DIM   96
#define LTOK  512
#define BLK   12
#define EPS   1e-8f

// pooled tokens token-major: [tensor(2)][b(2)][l(512)][c(32)]
__device__ float g_pooled[2 * BATCH * LTOK * CH];
// partial Grams: [b(2)][g(3: aa, bb, ab)][i(32)][j(32)]
__device__ float g_gram[BATCH * 3 * CH * CH];
__device__ unsigned int g_cnt;

// ---------------------------------------------------------------------------
// Kernel 1: pooling. One block per (tensor, b, c, pd, ph). 96 threads:
// f4 = tid%24 (float4 along w), rs = tid/24 -> contiguous d chunk, so all 36
// loads are affine immediate offsets from one base (front-batched LDG.128).
// Block 0 also zeroes the Gram accumulator + counter for this replay.
// ---------------------------------------------------------------------------
__global__ __launch_bounds__(96) void pool_kernel(const float* __restrict__ p1,
                                                  const float* __restrict__ p2)
{
    const int bid = blockIdx.x;
    if (bid == 0) {
        for (int i = threadIdx.x; i < BATCH * 3 * CH * CH; i += 96)
            g_gram[i] = 0.0f;
        if (threadIdx.x == 0) g_cnt = 0u;
    }

    const int ph = bid & 7;
    const int pd = (bid >> 3) & 7;
    const int c  = (bid >> 6) & 31;
    const int b  = (bid >> 11) & 1;
    const int t  = bid >> 12;

    const float* __restrict__ in = (t == 0) ? p1 : p2;

    const int tid = threadIdx.x;
    const int f4  = tid % 24;   // w = 4*f4
    const int rs  = tid / 24;   // 0..3 -> d in [3rs, 3rs+3)

    const float* __restrict__ base =
        in + ((size_t)(b * CH + c)) * (DIM * DIM * DIM)
           + (size_t)(pd * BLK + 3 * rs) * (DIM * DIM)
           + (size_t)ph * BLK * DIM
           + f4 * 4;

    float acc = 0.0f;
    #pragma unroll
    for (int d2 = 0; d2 < 3; ++d2) {
        #pragma unroll
        for (int h = 0; h < 12; ++h) {
            const float4 v = __ldcs(reinterpret_cast<const float4*>(
                base + d2 * (DIM * DIM) + h * DIM));
            acc += (v.x + v.y) + (v.z + v.w);
        }
    }

    __shared__ float sh[96];
    sh[tid] = acc;
    __syncthreads();

    if (tid < 8) {
        float s = 0.0f;
        #pragma unroll
        for (int r2 = 0; r2 < 4; ++r2)
            #pragma unroll
            for (int j = 0; j < 3; ++j)
                s += sh[r2 * 24 + tid * 3 + j];
        const int l = pd * 64 + ph * 8 + tid;
        g_pooled[(((size_t)t * BATCH + b) * LTOK + l) * CH + c] =
            s * (1.0f / (BLK * BLK * BLK));
    }
}

// ---------------------------------------------------------------------------
// Kernel 2: Gram accumulation + fused finalize.
// 32 blocks = 2 batches x 16 l-chunks (32 tokens each). 256 threads.
// Shared: channel-major normalized tokens sh[t][c][l], stride 33 (conflict-
// free). Each thread computes a 2x2 tile of each of the 3 Grams over its
// chunk's 32 l's (P reads broadcast across tj, Q reads 16 distinct banks),
// then atomicAdds partials. Last block reduces +/-||G||^2 and writes out.
// ---------------------------------------------------------------------------
#define LSTR 33
#define SIM_BLOCKS 32

__global__ __launch_bounds__(256) void sim_kernel(float* __restrict__ out)
{
    __shared__ float sh[2 * CH * LSTR];   // [t][c][l] : 8.4 KB
    __shared__ float wsum[8];
    __shared__ int is_last;

    const int b     = blockIdx.x >> 4;    // 0..1
    const int chunk = blockIdx.x & 15;    // 0..15
    const int l0    = chunk * 32;
    const int tid   = threadIdx.x;

    // Load 2 tensors x 32 tokens x 32 ch, transposed to channel-major.
    for (int idx = tid; idx < 2 * 32 * CH; idx += 256) {
        const int t = idx >> 10;
        const int l = (idx >> 5) & 31;
        const int c = idx & 31;
        sh[t * CH * LSTR + c * LSTR + l] =
            g_pooled[(((size_t)t * BATCH + b) * LTOK + l0 + l) * CH + c];
    }
    __syncthreads();

    // Normalize each token column (64 tokens: t in {0,1}, l in [0,32)).
    if (tid < 64) {
        const int t = tid >> 5;
        const int l = tid & 31;
        float* col = sh + t * CH * LSTR + l;
        float s = 0.0f;
        #pragma unroll
        for (int c = 0; c < CH; ++c) {
            const float v = col[c * LSTR];
            s += v * v;
        }
        const float r = 1.0f / sqrtf(fmaxf(s, EPS));
        #pragma unroll
        for (int c = 0; c < CH; ++c)
            col[c * LSTR] *= r;
    }
    __syncthreads();

    // 2x2 register-tiled Grams: (i,j) tile at (2ti, 2tj).
    const int tj = tid & 15;
    const int ti = tid >> 4;
    const float* __restrict__ A = sh;
    const float* __restrict__ B = sh + CH * LSTR;

    const float* Pg[3] = { A, B, A };
    const float* Qg[3] = { A, B, B };

    #pragma unroll
    for (int g = 0; g < 3; ++g) {
        const float* __restrict__ P = Pg[g];
        const float* __restrict__ Q = Qg[g];
        float a00 = 0.0f, a01 = 0.0f, a10 = 0.0f, a11 = 0.0f;
        #pragma unroll 8
        for (int l = 0; l < 32; ++l) {
            const float p0 = P[(2 * ti)     * LSTR + l];
            const float p1 = P[(2 * ti + 1) * LSTR + l];
            const float q0 = Q[(2 * tj)     * LSTR + l];
            const float q1 = Q[(2 * tj + 1) * LSTR + l];
            a00 += p0 * q0;  a01 += p0 * q1;
            a10 += p1 * q0;  a11 += p1 * q1;
        }
        float* dst = g_gram + ((size_t)b * 3 + g) * (CH * CH);
        atomicAdd(&dst[(2 * ti)     * CH + 2 * tj],     a00);
        atomicAdd(&dst[(2 * ti)     * CH + 2 * tj + 1], a01);
        atomicAdd(&dst[(2 * ti + 1) * CH + 2 * tj],     a10);
        atomicAdd(&dst[(2 * ti + 1) * CH + 2 * tj + 1], a11);
    }

    // Completion counter -> last block finalizes.
    __threadfence();
    __syncthreads();
    if (tid == 0) {
        const unsigned int old = atomicAdd(&g_cnt, 1u);
        is_last = (old == SIM_BLOCKS - 1) ? 1 : 0;
    }
    __syncthreads();
    if (!is_last) return;

    // loss = sum_b ( ||Gaa||^2 + ||Gbb||^2 - 2||Gab||^2 ) / (L^2 * B)
    float local = 0.0f;
    const volatile float* vg = (const volatile float*)g_gram;
    for (int i = tid; i < BATCH * 3 * CH * CH; i += 256) {
        const int g = (i >> 10) % 3;          // gram index within batch
        const float v = vg[i];
        const float w = (g == 2) ? -2.0f : 1.0f;
        local += w * v * v;
    }
    #pragma unroll
    for (int off = 16; off > 0; off >>= 1)
        local += __shfl_xor_sync(0xFFFFFFFFu, local, off);
    if ((tid & 31) == 0) wsum[tid >> 5] = local;
    __syncthreads();
    if (tid == 0) {
        float s = 0.0f;
        #pragma unroll
        for (int i = 0; i < 8; ++i) s += wsum[i];
        out[0] = s * (1.0f / ((float)LTOK * (float)LTOK * (float)BATCH));
    }
}

// ---------------------------------------------------------------------------
extern "C" void kernel_launch(void* const* d_in, const int* in_sizes, int n_in,
                              void* d_out, int out_size)
{
    const float* p1 = (const float*)d_in[0];
    const float* p2 = (const float*)d_in[1];
    float* out = (float*)d_out;

    pool_kernel<<<8192, 96>>>(p1, p2);   // 2*2*32*8*8 blocks
    sim_kernel<<<SIM_BLOCKS, 256>>>(out);
}

// round 9
// speedup vs baseline: 1.2067x; 1.0046x over previous
#include <cuda_runtime.h>
#include <cuda_bf16.h>

// p1, p2: [B=2, C=32, D=96, H=96, W=96] fp32
// pool to S=8 (cells 12^3), L = 512 tokens, C = 32 channels.
// loss = mean_b mean_{l,m} (cos_a[l,m] - cos_b[l,m])^2
//      = (1/(L^2 B)) * sum_b [ ||Ga||F^2 + ||Gb||F^2 - 2||Gx||F^2 ]
// with Ga = Ua^T Ua, Gb = Ub^T Ub, Gx = Ua^T Ub over unit-normalized tokens.

#define BATCH 2
#define CH    32
#define DIM   96
#define LTOK  512
#define BLK   12
#define EPS   1e-8f

// pooled tokens token-major: [tensor(2)][b(2)][l(512)][c(32)]
__device__ float g_pooled[2 * BATCH * LTOK * CH];
// partial Grams: [b(2)][g(3: aa, bb, ab)][i(32)][j(32)]
__device__ float g_gram[BATCH * 3 * CH * CH];
__device__ unsigned int g_cnt;

// ---------------------------------------------------------------------------
// Kernel 1: pooling. One block per (tensor, b, c, pd, ph). 96 threads:
// f4 = tid%24 (float4 along w), rs = tid/24 -> contiguous d chunk, so all 36
// loads are affine immediate offsets from one base (front-batched LDG.128).
// Block 0 also zeroes the Gram accumulator + counter for this replay.
// ---------------------------------------------------------------------------
__global__ __launch_bounds__(96) void pool_kernel(const float* __restrict__ p1,
                                                  const float* __restrict__ p2)
{
    const int bid = blockIdx.x;
    if (bid == 0) {
        for (int i = threadIdx.x; i < BATCH * 3 * CH * CH; i += 96)
            g_gram[i] = 0.0f;
        if (threadIdx.x == 0) g_cnt = 0u;
    }

    const int ph = bid & 7;
    const int pd = (bid >> 3) & 7;
    const int c  = (bid >> 6) & 31;
    const int b  = (bid >> 11) & 1;
    const int t  = bid >> 12;

    const float* __restrict__ in = (t == 0) ? p1 : p2;

    const int tid = threadIdx.x;
    const int f4  = tid % 24;   // w = 4*f4
    const int rs  = tid / 24;   // 0..3 -> d in [3rs, 3rs+3)

    const float* __restrict__ base =
        in + ((size_t)(b * CH + c)) * (DIM * DIM * DIM)
           + (size_t)(pd * BLK + 3 * rs) * (DIM * DIM)
           + (size_t)ph * BLK * DIM
           + f4 * 4;

    float acc = 0.0f;
    #pragma unroll
    for (int d2 = 0; d2 < 3; ++d2) {
        #pragma unroll
        for (int h = 0; h < 12; ++h) {
            const float4 v = __ldcs(reinterpret_cast<const float4*>(
                base + d2 * (DIM * DIM) + h * DIM));
            acc += (v.x + v.y) + (v.z + v.w);
        }
    }

    __shared__ float sh[96];
    sh[tid] = acc;
    __syncthreads();

    if (tid < 8) {
        float s = 0.0f;
        #pragma unroll
        for (int r2 = 0; r2 < 4; ++r2)
            #pragma unroll
            for (int j = 0; j < 3; ++j)
                s += sh[r2 * 24 + tid * 3 + j];
        const int l = pd * 64 + ph * 8 + tid;
        g_pooled[(((size_t)t * BATCH + b) * LTOK + l) * CH + c] =
            s * (1.0f / (BLK * BLK * BLK));
    }
}

// ---------------------------------------------------------------------------
// Kernel 2: Gram accumulation + fused finalize.
// 32 blocks = 2 batches x 16 l-chunks (32 tokens each). 256 threads.
// Shared: channel-major normalized tokens sh[t][c][l], stride 33 (conflict-
// free). Each thread computes a 2x2 tile of each of the 3 Grams over its
// chunk's 32 l's (P reads broadcast across tj, Q reads 16 distinct banks),
// then atomicAdds partials. Last block reduces +/-||G||^2 and writes out.
// ---------------------------------------------------------------------------
#define LSTR 33
#define SIM_BLOCKS 32

__global__ __launch_bounds__(256) void sim_kernel(float* __restrict__ out)
{
    __shared__ float sh[2 * CH * LSTR];   // [t][c][l] : 8.4 KB
    __shared__ float wsum[8];
    __shared__ int is_last;

    const int b     = blockIdx.x >> 4;    // 0..1
    const int chunk = blockIdx.x & 15;    // 0..15
    const int l0    = chunk * 32;
    const int tid   = threadIdx.x;

    // Load 2 tensors x 32 tokens x 32 ch, transposed to channel-major.
    for (int idx = tid; idx < 2 * 32 * CH; idx += 256) {
        const int t = idx >> 10;
        const int l = (idx >> 5) & 31;
        const int c = idx & 31;
        sh[t * CH * LSTR + c * LSTR + l] =
            g_pooled[(((size_t)t * BATCH + b) * LTOK + l0 + l) * CH + c];
    }
    __syncthreads();

    // Normalize each token column (64 tokens: t in {0,1}, l in [0,32)).
    if (tid < 64) {
        const int t = tid >> 5;
        const int l = tid & 31;
        float* col = sh + t * CH * LSTR + l;
        float s = 0.0f;
        #pragma unroll
        for (int c = 0; c < CH; ++c) {
            const float v = col[c * LSTR];
            s += v * v;
        }
        const float r = 1.0f / sqrtf(fmaxf(s, EPS));
        #pragma unroll
        for (int c = 0; c < CH; ++c)
            col[c * LSTR] *= r;
    }
    __syncthreads();

    // 2x2 register-tiled Grams: (i,j) tile at (2ti, 2tj).
    const int tj = tid & 15;
    const int ti = tid >> 4;
    const float* __restrict__ A = sh;
    const float* __restrict__ B = sh + CH * LSTR;

    const float* Pg[3] = { A, B, A };
    const float* Qg[3] = { A, B, B };

    #pragma unroll
    for (int g = 0; g < 3; ++g) {
        const float* __restrict__ P = Pg[g];
        const float* __restrict__ Q = Qg[g];
        float a00 = 0.0f, a01 = 0.0f, a10 = 0.0f, a11 = 0.0f;
        #pragma unroll 8
        for (int l = 0; l < 32; ++l) {
            const float p0 = P[(2 * ti)     * LSTR + l];
            const float p1 = P[(2 * ti + 1) * LSTR + l];
            const float q0 = Q[(2 * tj)     * LSTR + l];
            const float q1 = Q[(2 * tj + 1) * LSTR + l];
            a00 += p0 * q0;  a01 += p0 * q1;
            a10 += p1 * q0;  a11 += p1 * q1;
        }
        float* dst = g_gram + ((size_t)b * 3 + g) * (CH * CH);
        atomicAdd(&dst[(2 * ti)     * CH + 2 * tj],     a00);
        atomicAdd(&dst[(2 * ti)     * CH + 2 * tj + 1], a01);
        atomicAdd(&dst[(2 * ti + 1) * CH + 2 * tj],     a10);
        atomicAdd(&dst[(2 * ti + 1) * CH + 2 * tj + 1], a11);
    }

    // Completion counter -> last block finalizes.
    __threadfence();
    __syncthreads();
    if (tid == 0) {
        const unsigned int old = atomicAdd(&g_cnt, 1u);
        is_last = (old == SIM_BLOCKS - 1) ? 1 : 0;
    }
    __syncthreads();
    if (!is_last) return;

    // loss = sum_b ( ||Gaa||^2 + ||Gbb||^2 - 2||Gab||^2 ) / (L^2 * B)
    float local = 0.0f;
    const volatile float* vg = (const volatile float*)g_gram;
    for (int i = tid; i < BATCH * 3 * CH * CH; i += 256) {
        const int g = (i >> 10) % 3;          // gram index within batch
        const float v = vg[i];
        const float w = (g == 2) ? -2.0f : 1.0f;
        local += w * v * v;
    }
    #pragma unroll
    for (int off = 16; off > 0; off >>= 1)
        local += __shfl_xor_sync(0xFFFFFFFFu, local, off);
    if ((tid & 31) == 0) wsum[tid >> 5] = local;
    __syncthreads();
    if (tid == 0) {
        float s = 0.0f;
        #pragma unroll
        for (int i = 0; i < 8; ++i) s += wsum[i];
        out[0] = s * (1.0f / ((float)LTOK * (float)LTOK * (float)BATCH));
    }
}

// ---------------------------------------------------------------------------
extern "C" void kernel_launch(void* const* d_in, const int* in_sizes, int n_in,
                              void* d_out, int out_size)
{
    const float* p1 = (const float*)d_in[0];
    const float* p2 = (const float*)d_in[1];
    float* out = (float*)d_out;

    pool_kernel<<<8192, 96>>>(p1, p2);   // 2*2*32*8*8 blocks
    sim_kernel<<<SIM_BLOCKS, 256>>>(out);
}

// round 10
// speedup vs baseline: 1.2153x; 1.0071x over previous
#include <cuda_runtime.h>
#include <cuda_bf16.h>

// p1, p2: [B=2, C=32, D=96, H=96, W=96] fp32
// pool to S=8 (cells 12^3), L = 512 tokens, C = 32 channels.
// loss = mean_b mean_{l,m} (cos_a[l,m] - cos_b[l,m])^2
//      = (1/(L^2 B)) * sum_b [ ||Ga||F^2 + ||Gb||F^2 - 2||Gx||F^2 ]
// with Ga = Ua^T Ua, Gb = Ub^T Ub, Gx = Ua^T Ub over unit-normalized tokens.

#define BATCH 2
#define CH    32
#define DIM   96
#define LTOK  512
#define BLK   12
#define EPS   1e-8f

// pooled tokens token-major: [tensor(2)][b(2)][l(512)][c(32)]
__device__ float g_pooled[2 * BATCH * LTOK * CH];
// partial Grams: [b(2)][g(3: aa, bb, ab)][i(32)][j(32)]
__device__ float g_gram[BATCH * 3 * CH * CH];
__device__ unsigned int g_cnt;

// ---------------------------------------------------------------------------
// Kernel 1: pooling. One block per (tensor, b, c, pd, ph). 96 threads:
// f4 = tid%24 (float4 along w), rs = tid/24 -> contiguous d chunk, so all 36
// loads are affine immediate offsets from one base (front-batched LDG.128).
// Block 0 also zeroes the Gram accumulator + counter for this replay.
// ---------------------------------------------------------------------------
__global__ __launch_bounds__(96) void pool_kernel(const float* __restrict__ p1,
                                                  const float* __restrict__ p2)
{
    const int bid = blockIdx.x;
    if (bid == 0) {
        for (int i = threadIdx.x; i < BATCH * 3 * CH * CH; i += 96)
            g_gram[i] = 0.0f;
        if (threadIdx.x == 0) g_cnt = 0u;
    }

    const int ph = bid & 7;
    const int pd = (bid >> 3) & 7;
    const int c  = (bid >> 6) & 31;
    const int b  = (bid >> 11) & 1;
    const int t  = bid >> 12;

    const float* __restrict__ in = (t == 0) ? p1 : p2;

    const int tid = threadIdx.x;
    const int f4  = tid % 24;   // w = 4*f4
    const int rs  = tid / 24;   // 0..3 -> d in [3rs, 3rs+3)

    const float* __restrict__ base =
        in + ((size_t)(b * CH + c)) * (DIM * DIM * DIM)
           + (size_t)(pd * BLK + 3 * rs) * (DIM * DIM)
           + (size_t)ph * BLK * DIM
           + f4 * 4;

    float acc = 0.0f;
    #pragma unroll
    for (int d2 = 0; d2 < 3; ++d2) {
        #pragma unroll
        for (int h = 0; h < 12; ++h) {
            const float4 v = __ldcs(reinterpret_cast<const float4*>(
                base + d2 * (DIM * DIM) + h * DIM));
            acc += (v.x + v.y) + (v.z + v.w);
        }
    }

    __shared__ float sh[96];
    sh[tid] = acc;
    __syncthreads();

    if (tid < 8) {
        float s = 0.0f;
        #pragma unroll
        for (int r2 = 0; r2 < 4; ++r2)
            #pragma unroll
            for (int j = 0; j < 3; ++j)
                s += sh[r2 * 24 + tid * 3 + j];
        const int l = pd * 64 + ph * 8 + tid;
        g_pooled[(((size_t)t * BATCH + b) * LTOK + l) * CH + c] =
            s * (1.0f / (BLK * BLK * BLK));
    }
}

// ---------------------------------------------------------------------------
// Kernel 2: Gram accumulation + fused finalize.
// 32 blocks = 2 batches x 16 l-chunks (32 tokens each). 256 threads.
// Shared: channel-major normalized tokens sh[t][c][l], stride 33 (conflict-
// free). Each thread computes a 2x2 tile of each of the 3 Grams over its
// chunk's 32 l's (P reads broadcast across tj, Q reads 16 distinct banks),
// then atomicAdds partials. Last block reduces +/-||G||^2 and writes out.
// ---------------------------------------------------------------------------
#define LSTR 33
#define SIM_BLOCKS 32

__global__ __launch_bounds__(256) void sim_kernel(float* __restrict__ out)
{
    __shared__ float sh[2 * CH * LSTR];   // [t][c][l] : 8.4 KB
    __shared__ float wsum[8];
    __shared__ int is_last;

    const int b     = blockIdx.x >> 4;    // 0..1
    const int chunk = blockIdx.x & 15;    // 0..15
    const int l0    = chunk * 32;
    const int tid   = threadIdx.x;

    // Load 2 tensors x 32 tokens x 32 ch, transposed to channel-major.
    for (int idx = tid; idx < 2 * 32 * CH; idx += 256) {
        const int t = idx >> 10;
        const int l = (idx >> 5) & 31;
        const int c = idx & 31;
        sh[t * CH * LSTR + c * LSTR + l] =
            g_pooled[(((size_t)t * BATCH + b) * LTOK + l0 + l) * CH + c];
    }
    __syncthreads();

    // Normalize each token column (64 tokens: t in {0,1}, l in [0,32)).
    if (tid < 64) {
        const int t = tid >> 5;
        const int l = tid & 31;
        float* col = sh + t * CH * LSTR + l;
        float s = 0.0f;
        #pragma unroll
        for (int c = 0; c < CH; ++c) {
            const float v = col[c * LSTR];
            s += v * v;
        }
        const float r = 1.0f / sqrtf(fmaxf(s, EPS));
        #pragma unroll
        for (int c = 0; c < CH; ++c)
            col[c * LSTR] *= r;
    }
    __syncthreads();

    // 2x2 register-tiled Grams: (i,j) tile at (2ti, 2tj).
    const int tj = tid & 15;
    const int ti = tid >> 4;
    const float* __restrict__ A = sh;
    const float* __restrict__ B = sh + CH * LSTR;

    const float* Pg[3] = { A, B, A };
    const float* Qg[3] = { A, B, B };

    #pragma unroll
    for (int g = 0; g < 3; ++g) {
        const float* __restrict__ P = Pg[g];
        const float* __restrict__ Q = Qg[g];
        float a00 = 0.0f, a01 = 0.0f, a10 = 0.0f, a11 = 0.0f;
        #pragma unroll 8
        for (int l = 0; l < 32; ++l) {
            const float p0 = P[(2 * ti)     * LSTR + l];
            const float p1 = P[(2 * ti + 1) * LSTR + l];
            const float q0 = Q[(2 * tj)     * LSTR + l];
            const float q1 = Q[(2 * tj + 1) * LSTR + l];
            a00 += p0 * q0;  a01 += p0 * q1;
            a10 += p1 * q0;  a11 += p1 * q1;
        }
        float* dst = g_gram + ((size_t)b * 3 + g) * (CH * CH);
        atomicAdd(&dst[(2 * ti)     * CH + 2 * tj],     a00);
        atomicAdd(&dst[(2 * ti)     * CH + 2 * tj + 1], a01);
        atomicAdd(&dst[(2 * ti + 1) * CH + 2 * tj],     a10);
        atomicAdd(&dst[(2 * ti + 1) * CH + 2 * tj + 1], a11);
    }

    // Completion counter -> last block finalizes.
    __threadfence();
    __syncthreads();
    if (tid == 0) {
        const unsigned int old = atomicAdd(&g_cnt, 1u);
        is_last = (old == SIM_BLOCKS - 1) ? 1 : 0;
    }
    __syncthreads();
    if (!is_last) return;

    // loss = sum_b ( ||Gaa||^2 + ||Gbb||^2 - 2||Gab||^2 ) / (L^2 * B)
    float local = 0.0f;
    const volatile float* vg = (const volatile float*)g_gram;
    for (int i = tid; i < BATCH * 3 * CH * CH; i += 256) {
        const int g = (i >> 10) % 3;          // gram index within batch
        const float v = vg[i];
        const float w = (g == 2) ? -2.0f : 1.0f;
        local += w * v * v;
    }
    #pragma unroll
    for (int off = 16; off > 0; off >>= 1)
        local += __shfl_xor_sync(0xFFFFFFFFu, local, off);
    if ((tid & 31) == 0) wsum[tid >> 5] = local;
    __syncthreads();
    if (tid == 0) {
        float s = 0.0f;
        #pragma unroll
        for (int i = 0; i < 8; ++i) s += wsum[i];
        out[0] = s * (1.0f / ((float)LTOK * (float)LTOK * (float)BATCH));
    }
}

// ---------------------------------------------------------------------------
extern "C" void kernel_launch(void* const* d_in, const int* in_sizes, int n_in,
                              void* d_out, int out_size)
{
    const float* p1 = (const float*)d_in[0];
    const float* p2 = (const float*)d_in[1];
    float* out = (float*)d_out;

    pool_kernel<<<8192, 96>>>(p1, p2);   // 2*2*32*8*8 blocks
    sim_kernel<<<SIM_BLOCKS, 256>>>(out);
}